// round 13
// baseline (speedup 1.0000x reference)
#include <cuda_runtime.h>
#include <cuda_bf16.h>
#include <math.h>
#include <stdint.h>

// Problem constants
#define NN_ 4096
#define FF_ 512
#define DD_ 512
#define DFF_ 2048
#define LL_ 4
#define HH_ 8

// ---------------- scratch (__device__ globals; no allocation allowed) ----------------
__device__ float g_h1[NN_ * DD_];
__device__ float g_h2[NN_ * DD_];
__device__ float g_cat[NN_ * 2 * FF_];
__device__ float g_emb[NN_ * DD_];
__device__ float g_y[NN_ * DD_];
__device__ float g_q[NN_ * DD_];
__device__ float g_k[NN_ * DD_];
__device__ float g_v[NN_ * DD_];
__device__ float g_o[NN_ * DD_];
__device__ float g_ffn[NN_ * DFF_];
__device__ float g_err[NN_];
__device__ float g_mnmx[2];

enum { EP_NONE = 0, EP_BIAS = 1, EP_BIAS_RES = 2, EP_GELU = 3, EP_RELU = 4 };

// ================= low-level helpers =================
__device__ __forceinline__ uint32_t smem_u32(const void* p) {
    uint32_t a;
    asm("{ .reg .u64 t; cvta.to.shared.u64 t, %1; cvt.u32.u64 %0, t; }" : "=r"(a) : "l"(p));
    return a;
}

__device__ __forceinline__ void ldsm4(uint32_t* r, uint32_t a) {
    asm volatile("ldmatrix.sync.aligned.m8n8.x4.shared.b16 {%0,%1,%2,%3}, [%4];"
                 : "=r"(r[0]), "=r"(r[1]), "=r"(r[2]), "=r"(r[3]) : "r"(a));
}
__device__ __forceinline__ void ldsm4t(uint32_t* r, uint32_t a) {
    asm volatile("ldmatrix.sync.aligned.m8n8.x4.trans.shared.b16 {%0,%1,%2,%3}, [%4];"
                 : "=r"(r[0]), "=r"(r[1]), "=r"(r[2]), "=r"(r[3]) : "r"(a));
}

__device__ __forceinline__ void mma16816(float* d, const uint32_t* a, uint32_t b0, uint32_t b1) {
    asm volatile(
        "mma.sync.aligned.m16n8k16.row.col.f32.bf16.bf16.f32 "
        "{%0,%1,%2,%3}, {%4,%5,%6,%7}, {%8,%9}, {%0,%1,%2,%3};"
        : "+f"(d[0]), "+f"(d[1]), "+f"(d[2]), "+f"(d[3])
        : "r"(a[0]), "r"(a[1]), "r"(a[2]), "r"(a[3]), "r"(b0), "r"(b1));
}

__device__ __forceinline__ void mma_tf32(float* d, const uint32_t* a, uint32_t b0, uint32_t b1) {
    asm volatile(
        "mma.sync.aligned.m16n8k8.row.col.f32.tf32.tf32.f32 "
        "{%0,%1,%2,%3}, {%4,%5,%6,%7}, {%8,%9}, {%0,%1,%2,%3};"
        : "+f"(d[0]), "+f"(d[1]), "+f"(d[2]), "+f"(d[3])
        : "r"(a[0]), "r"(a[1]), "r"(a[2]), "r"(a[3]), "r"(b0), "r"(b1));
}

__device__ __forceinline__ uint32_t f2tf32(float x) {
    uint32_t r;
    asm("cvt.rna.tf32.f32 %0, %1;" : "=r"(r) : "f"(x));
    return r;
}

__device__ __forceinline__ uint32_t cvt_bf16x2(float e0, float e1) {
    uint32_t r;
    asm("cvt.rn.bf16x2.f32 %0, %1, %2;" : "=r"(r) : "f"(e1), "f"(e0));
    return r;
}

// hi/lo split of a pair: hi = top-16-bit truncation (exact), lo = bf16_rn(x - hi)
__device__ __forceinline__ void split_pair(float e0, float e1, uint32_t& hw, uint32_t& lw) {
    uint32_t b0 = __float_as_uint(e0), b1 = __float_as_uint(e1);
    hw = __byte_perm(b0, b1, 0x7632);
    float l0 = e0 - __uint_as_float(b0 & 0xFFFF0000u);
    float l1 = e1 - __uint_as_float(b1 & 0xFFFF0000u);
    lw = cvt_bf16x2(l0, l1);
}

// ================= single-pass TF32 GEMM, 64x64 tile, 4 warps, occ>=4 =================
// C[M,N] = A[M,K] B^T + epilogue (NT: B is [N,K] row-major).
// Warps 2(m) x 2(n); warp tile 32x32 = 2 mt x 4 nt of m16n8k8; K-chunk 32.
__global__ void __launch_bounds__(128, 4)
gemm_tf(const float* __restrict__ A, const float* __restrict__ B,
        const float* __restrict__ bias, const float* __restrict__ extra,
        float* __restrict__ C,
        int M, int N, int K, int lda, int ldb, int ldc, int mode)
{
    __shared__ uint32_t sA[64][36];
    __shared__ uint32_t sB[64][36];

    const int tid = threadIdx.x, lane = tid & 31, wid = tid >> 5;
    const int wm = wid >> 1, wn = wid & 1;
    const int bm0 = blockIdx.y * 64, bn0 = blockIdx.x * 64;

    float acc[2][4][4];
#pragma unroll
    for (int i = 0; i < 2; i++)
#pragma unroll
        for (int j = 0; j < 4; j++)
#pragma unroll
            for (int e = 0; e < 4; e++) acc[i][j][e] = 0.0f;

    const int nc = K / 32;
    const int lrow = tid >> 3, lc4 = (tid & 7) * 4;
    float4 ra[4], rb[4];

#pragma unroll
    for (int i = 0; i < 4; i++) {
        int row = lrow + i * 16;
        ra[i] = *reinterpret_cast<const float4*>(&A[(long long)(bm0 + row) * lda + lc4]);
        rb[i] = *reinterpret_cast<const float4*>(&B[(long long)(bn0 + row) * ldb + lc4]);
    }

    for (int c = 0; c < nc; c++) {
#pragma unroll
        for (int i = 0; i < 4; i++) {
            int row = lrow + i * 16;
            uint4 ua = make_uint4(f2tf32(ra[i].x), f2tf32(ra[i].y), f2tf32(ra[i].z), f2tf32(ra[i].w));
            uint4 ub = make_uint4(f2tf32(rb[i].x), f2tf32(rb[i].y), f2tf32(rb[i].z), f2tf32(rb[i].w));
            *reinterpret_cast<uint4*>(&sA[row][lc4]) = ua;
            *reinterpret_cast<uint4*>(&sB[row][lc4]) = ub;
        }
        __syncthreads();

        if (c + 1 < nc) {
            const int k0 = (c + 1) * 32;
#pragma unroll
            for (int i = 0; i < 4; i++) {
                int row = lrow + i * 16;
                ra[i] = *reinterpret_cast<const float4*>(&A[(long long)(bm0 + row) * lda + k0 + lc4]);
                rb[i] = *reinterpret_cast<const float4*>(&B[(long long)(bn0 + row) * ldb + k0 + lc4]);
            }
        }

        const int g4 = lane >> 2, l4 = lane & 3;
#pragma unroll
        for (int kk = 0; kk < 4; kk++) {
            const int kc = kk * 8 + l4;
            uint32_t af[2][4];
#pragma unroll
            for (int mt = 0; mt < 2; mt++) {
                const int r = wm * 32 + mt * 16 + g4;
                af[mt][0] = sA[r][kc];
                af[mt][1] = sA[r + 8][kc];
                af[mt][2] = sA[r][kc + 4];
                af[mt][3] = sA[r + 8][kc + 4];
            }
            uint32_t bf[4][2];
#pragma unroll
            for (int nt = 0; nt < 4; nt++) {
                const int n = wn * 32 + nt * 8 + g4;
                bf[nt][0] = sB[n][kc];
                bf[nt][1] = sB[n][kc + 4];
            }
#pragma unroll
            for (int mt = 0; mt < 2; mt++)
#pragma unroll
                for (int nt = 0; nt < 4; nt++)
                    mma_tf32(acc[mt][nt], af[mt], bf[nt][0], bf[nt][1]);
        }
        __syncthreads();
    }

#pragma unroll
    for (int mt = 0; mt < 2; mt++)
#pragma unroll
        for (int nt = 0; nt < 4; nt++) {
            const int r0 = bm0 + wm * 32 + mt * 16 + (lane >> 2);
            const int cc = bn0 + wn * 32 + nt * 8 + 2 * (lane & 3);
#pragma unroll
            for (int h = 0; h < 2; h++) {
                const int r = r0 + h * 8;
                float v0 = acc[mt][nt][2 * h], v1 = acc[mt][nt][2 * h + 1];
                const long long off = (long long)r * ldc + cc;
                if (mode == EP_BIAS) {
                    v0 += bias[cc]; v1 += bias[cc + 1];
                } else if (mode == EP_BIAS_RES) {
                    v0 += bias[cc] + extra[off]; v1 += bias[cc + 1] + extra[off + 1];
                } else if (mode == EP_GELU) {
                    v0 += bias[cc]; v1 += bias[cc + 1];
                    v0 = 0.5f * v0 * (1.0f + erff(v0 * 0.7071067811865475f));
                    v1 = 0.5f * v1 * (1.0f + erff(v1 * 0.7071067811865475f));
                } else if (mode == EP_RELU) {
                    v0 = fmaxf(v0 + bias[cc], 0.0f); v1 = fmaxf(v1 + bias[cc + 1], 0.0f);
                }
                *reinterpret_cast<float2*>(&C[off]) = make_float2(v0, v1);
            }
        }
}

// ================= PPR split-bf16 GEMM, 64x64 tile, 4 warps, occ>=4 (NN) =================
// C = alpha*(A[M,K] @ B[K,N]) + beta*extra. 3-pass hi/lo bf16 (error ~2^-17).
__global__ void __launch_bounds__(128, 4)
ppr_gemm(const float* __restrict__ A, const float* __restrict__ B,
         const float* __restrict__ extra, float* __restrict__ C,
         int M, int N, int K, int lda, int ldb, int ldc, float alpha, float beta)
{
    // planes: Ah | Al | Bh | Bl, each 64 rows x 40 bf16 (80 B rows)
    constexpr int PL = 64 * 80;
    __shared__ __align__(16) char smbuf[4 * PL];

    const uint32_t sbase = smem_u32(smbuf);
    const int tid = threadIdx.x, lane = tid & 31, wid = tid >> 5;
    const int wm = wid >> 1, wn = wid & 1;
    const int bm0 = blockIdx.y * 64, bn0 = blockIdx.x * 64;

    float acc[2][4][4];
#pragma unroll
    for (int i = 0; i < 2; i++)
#pragma unroll
        for (int j = 0; j < 4; j++)
#pragma unroll
            for (int e = 0; e < 4; e++) acc[i][j][e] = 0.0f;

    const int nc = K / 32;
    const int arow = tid >> 3, ac4 = (tid & 7) * 4;   // A: 64 rows x 32 cols
    const int bk = tid >> 4, bn4 = (tid & 15) * 4;    // B: 32 k-rows x 64 n-cols
    float4 ra[4], rb[4];

#pragma unroll
    for (int i = 0; i < 4; i++) {
        ra[i] = *reinterpret_cast<const float4*>(&A[(long long)(bm0 + arow + i * 16) * lda + ac4]);
        rb[i] = *reinterpret_cast<const float4*>(&B[(long long)(bk + i * 8) * ldb + bn0 + bn4]);
    }

    for (int c = 0; c < nc; c++) {
        // A tile -> hi/lo planes
#pragma unroll
        for (int i = 0; i < 4; i++) {
            uint32_t h0, l0, h1, l1;
            split_pair(ra[i].x, ra[i].y, h0, l0);
            split_pair(ra[i].z, ra[i].w, h1, l1);
            uint32_t off = (arow + i * 16) * 80 + ac4 * 2;
            *reinterpret_cast<uint2*>(smbuf + off) = make_uint2(h0, h1);
            *reinterpret_cast<uint2*>(smbuf + PL + off) = make_uint2(l0, l1);
        }
        // B tile -> transposed [n][k] hi/lo planes
#pragma unroll
        for (int i = 0; i < 4; i++) {
            const int k = bk + i * 8;
            float e[4] = {rb[i].x, rb[i].y, rb[i].z, rb[i].w};
#pragma unroll
            for (int j = 0; j < 4; j++) {
                uint32_t xb = __float_as_uint(e[j]);
                float lo = e[j] - __uint_as_float(xb & 0xFFFF0000u);
                uint32_t off = (bn4 + j) * 80 + k * 2;
                *reinterpret_cast<uint16_t*>(smbuf + 2 * PL + off) = (uint16_t)(xb >> 16);
                __nv_bfloat16 bl = __float2bfloat16(lo);
                *reinterpret_cast<uint16_t*>(smbuf + 3 * PL + off) =
                    *reinterpret_cast<uint16_t*>(&bl);
            }
        }
        __syncthreads();

        if (c + 1 < nc) {
            const int k0 = (c + 1) * 32;
#pragma unroll
            for (int i = 0; i < 4; i++) {
                ra[i] = *reinterpret_cast<const float4*>(
                    &A[(long long)(bm0 + arow + i * 16) * lda + k0 + ac4]);
                rb[i] = *reinterpret_cast<const float4*>(
                    &B[(long long)(k0 + bk + i * 8) * ldb + bn0 + bn4]);
            }
        }

        const uint32_t aAddr = sbase + (wm * 32 + (lane & 15)) * 80 + (((lane & 16) ? 8 : 0)) * 2;
        const uint32_t bAddr = sbase + 2 * PL +
                               (wn * 32 + (lane & 7) + ((lane & 16) ? 8 : 0)) * 80 +
                               (((lane & 8) ? 8 : 0)) * 2;

#pragma unroll
        for (int kk = 0; kk < 2; kk++) {
            uint32_t ah[2][4], al[2][4];
#pragma unroll
            for (int mt = 0; mt < 2; mt++) {
                uint32_t adr = aAddr + mt * 16 * 80 + kk * 32;
                ldsm4(ah[mt], adr);
                ldsm4(al[mt], adr + PL);
            }
            uint32_t bh[4][2], bl[4][2];
#pragma unroll
            for (int p = 0; p < 2; p++) {
                uint32_t r[4];
                uint32_t adr = bAddr + p * 16 * 80 + kk * 32;
                ldsm4(r, adr);
                bh[2 * p][0] = r[0]; bh[2 * p][1] = r[1];
                bh[2 * p + 1][0] = r[2]; bh[2 * p + 1][1] = r[3];
                ldsm4(r, adr + PL);
                bl[2 * p][0] = r[0]; bl[2 * p][1] = r[1];
                bl[2 * p + 1][0] = r[2]; bl[2 * p + 1][1] = r[3];
            }
#pragma unroll
            for (int mt = 0; mt < 2; mt++)
#pragma unroll
                for (int nt = 0; nt < 4; nt++) {
                    mma16816(acc[mt][nt], ah[mt], bh[nt][0], bh[nt][1]);
                    mma16816(acc[mt][nt], ah[mt], bl[nt][0], bl[nt][1]);
                    mma16816(acc[mt][nt], al[mt], bh[nt][0], bh[nt][1]);
                }
        }
        __syncthreads();
    }

#pragma unroll
    for (int mt = 0; mt < 2; mt++)
#pragma unroll
        for (int nt = 0; nt < 4; nt++) {
            const int r0 = bm0 + wm * 32 + mt * 16 + (lane >> 2);
            const int cc = bn0 + wn * 32 + nt * 8 + 2 * (lane & 3);
#pragma unroll
            for (int h = 0; h < 2; h++) {
                const int r = r0 + h * 8;
                const long long off = (long long)r * ldc + cc;
                float v0 = alpha * acc[mt][nt][2 * h] + beta * extra[off];
                float v1 = alpha * acc[mt][nt][2 * h + 1] + beta * extra[off + 1];
                *reinterpret_cast<float2*>(&C[off]) = make_float2(v0, v1);
            }
        }
}

// ================= fused flash attention (unchanged; validated R11) =================
__global__ void __launch_bounds__(256)
flash_kernel(const float* __restrict__ Q, const float* __restrict__ K,
             const float* __restrict__ V, float* __restrict__ O)
{
    __shared__ __align__(16) char sQh[64 * 144], sQl[64 * 144];
    __shared__ __align__(16) char sKVh[64 * 144], sKVl[64 * 144];
    __shared__ __align__(16) char sP[64 * 144];
    __shared__ float redM[64][4];
    __shared__ float redS[64][4];

    const int tid = threadIdx.x, lane = tid & 31, wid = tid >> 5;
    const int wm = wid >> 2, wn = wid & 3;
    const int q0 = blockIdx.x * 64;
    const int hc = blockIdx.y * 64;

    const uint32_t bQh = smem_u32(sQh), bQl = smem_u32(sQl);
    const uint32_t bKh = smem_u32(sKVh), bKl = smem_u32(sKVl);
    const uint32_t bP = smem_u32(sP);

#pragma unroll
    for (int i = 0; i < 4; i++) {
        int idx = tid + i * 256;
        int row = idx >> 4, c4 = (idx & 15) * 4;
        float4 u = *reinterpret_cast<const float4*>(&Q[(long long)(q0 + row) * DD_ + hc + c4]);
        uint32_t h0, l0, h1, l1;
        split_pair(u.x, u.y, h0, l0);
        split_pair(u.z, u.w, h1, l1);
        uint32_t off = row * 144 + c4 * 2;
        *reinterpret_cast<uint2*>(sQh + off) = make_uint2(h0, h1);
        *reinterpret_cast<uint2*>(sQl + off) = make_uint2(l0, l1);
    }

    float acc_o[2][2][4];
    float m_run[2][2], l_run[2][2];
#pragma unroll
    for (int mt = 0; mt < 2; mt++) {
#pragma unroll
        for (int nt = 0; nt < 2; nt++)
#pragma unroll
            for (int e = 0; e < 4; e++) acc_o[mt][nt][e] = 0.0f;
        m_run[mt][0] = m_run[mt][1] = -1e30f;
        l_run[mt][0] = l_run[mt][1] = 0.0f;
    }

    const int rbase = wm * 32 + (lane >> 2);

    for (int c = 0; c < NN_ / 64; c++) {
        __syncthreads();

#pragma unroll
        for (int i = 0; i < 4; i++) {
            int idx = tid + i * 256;
            int row = idx >> 4, c4 = (idx & 15) * 4;
            float4 u = *reinterpret_cast<const float4*>(
                &K[(long long)(c * 64 + row) * DD_ + hc + c4]);
            uint32_t h0, l0, h1, l1;
            split_pair(u.x, u.y, h0, l0);
            split_pair(u.z, u.w, h1, l1);
            uint32_t off = row * 144 + c4 * 2;
            *reinterpret_cast<uint2*>(sKVh + off) = make_uint2(h0, h1);
            *reinterpret_cast<uint2*>(sKVl + off) = make_uint2(l0, l1);
        }
        __syncthreads();

        float s[2][2][4];
#pragma unroll
        for (int mt = 0; mt < 2; mt++)
#pragma unroll
            for (int nt = 0; nt < 2; nt++)
#pragma unroll
                for (int e = 0; e < 4; e++) s[mt][nt][e] = 0.0f;

#pragma unroll
        for (int kk = 0; kk < 4; kk++) {
            const uint32_t colA = (kk * 16 + ((lane & 16) ? 8 : 0)) * 2;
            uint32_t qh[2][4], ql[2][4];
#pragma unroll
            for (int mt = 0; mt < 2; mt++) {
                uint32_t roff = (wm * 32 + mt * 16 + (lane & 15)) * 144 + colA;
                ldsm4(qh[mt], bQh + roff);
                ldsm4(ql[mt], bQl + roff);
            }
            uint32_t kh[4], kl[4];
            {
                uint32_t roff = (wn * 16 + (lane & 7) + ((lane & 16) ? 8 : 0)) * 144 +
                                (kk * 16 + ((lane & 8) ? 8 : 0)) * 2;
                ldsm4(kh, bKh + roff);
                ldsm4(kl, bKl + roff);
            }
#pragma unroll
            for (int mt = 0; mt < 2; mt++) {
                mma16816(s[mt][0], qh[mt], kh[0], kh[1]);
                mma16816(s[mt][1], qh[mt], kh[2], kh[3]);
                mma16816(s[mt][0], qh[mt], kl[0], kl[1]);
                mma16816(s[mt][1], qh[mt], kl[2], kl[3]);
                mma16816(s[mt][0], ql[mt], kh[0], kh[1]);
                mma16816(s[mt][1], ql[mt], kh[2], kh[3]);
            }
        }

#pragma unroll
        for (int mt = 0; mt < 2; mt++)
#pragma unroll
            for (int rh = 0; rh < 2; rh++) {
                float mp = fmaxf(fmaxf(s[mt][0][2 * rh], s[mt][0][2 * rh + 1]),
                                 fmaxf(s[mt][1][2 * rh], s[mt][1][2 * rh + 1]));
                mp = fmaxf(mp, __shfl_xor_sync(0xffffffffu, mp, 1));
                mp = fmaxf(mp, __shfl_xor_sync(0xffffffffu, mp, 2));
                if ((lane & 3) == 0) redM[rbase + mt * 16 + 8 * rh][wn] = mp;
            }
        __syncthreads();

        float f[2][2], sum_p[2][2];
#pragma unroll
        for (int mt = 0; mt < 2; mt++)
#pragma unroll
            for (int rh = 0; rh < 2; rh++) {
                const int row = rbase + mt * 16 + 8 * rh;
                float mc = fmaxf(fmaxf(redM[row][0], redM[row][1]),
                                 fmaxf(redM[row][2], redM[row][3]));
                float mn = fmaxf(m_run[mt][rh], mc);
                f[mt][rh] = __expf(m_run[mt][rh] - mn);
                m_run[mt][rh] = mn;
                sum_p[mt][rh] = 0.0f;
            }

#pragma unroll
        for (int mt = 0; mt < 2; mt++)
#pragma unroll
            for (int nt = 0; nt < 2; nt++)
#pragma unroll
                for (int rh = 0; rh < 2; rh++) {
                    float p0 = __expf(s[mt][nt][2 * rh] - m_run[mt][rh]);
                    float p1 = __expf(s[mt][nt][2 * rh + 1] - m_run[mt][rh]);
                    sum_p[mt][rh] += p0 + p1;
                    const int row = rbase + mt * 16 + 8 * rh;
                    const int col = wn * 16 + nt * 8 + 2 * (lane & 3);
                    *reinterpret_cast<uint32_t*>(sP + row * 144 + col * 2) = cvt_bf16x2(p0, p1);
                }
#pragma unroll
        for (int mt = 0; mt < 2; mt++)
#pragma unroll
            for (int nt = 0; nt < 2; nt++)
#pragma unroll
                for (int e = 0; e < 4; e++) acc_o[mt][nt][e] *= f[mt][e >> 1];

#pragma unroll
        for (int mt = 0; mt < 2; mt++)
#pragma unroll
            for (int rh = 0; rh < 2; rh++) {
                float sp = sum_p[mt][rh];
                sp += __shfl_xor_sync(0xffffffffu, sp, 1);
                sp += __shfl_xor_sync(0xffffffffu, sp, 2);
                if ((lane & 3) == 0) redS[rbase + mt * 16 + 8 * rh][wn] = sp;
            }
        __syncthreads();
#pragma unroll
        for (int mt = 0; mt < 2; mt++)
#pragma unroll
            for (int rh = 0; rh < 2; rh++) {
                const int row = rbase + mt * 16 + 8 * rh;
                float sc = redS[row][0] + redS[row][1] + redS[row][2] + redS[row][3];
                l_run[mt][rh] = l_run[mt][rh] * f[mt][rh] + sc;
            }

#pragma unroll
        for (int i = 0; i < 4; i++) {
            int idx = tid + i * 256;
            int row = idx >> 4, c4 = (idx & 15) * 4;
            float4 u = *reinterpret_cast<const float4*>(
                &V[(long long)(c * 64 + row) * DD_ + hc + c4]);
            uint32_t h0, l0, h1, l1;
            split_pair(u.x, u.y, h0, l0);
            split_pair(u.z, u.w, h1, l1);
            uint32_t off = row * 144 + c4 * 2;
            *reinterpret_cast<uint2*>(sKVh + off) = make_uint2(h0, h1);
            *reinterpret_cast<uint2*>(sKVl + off) = make_uint2(l0, l1);
        }
        __syncthreads();

#pragma unroll
        for (int kk = 0; kk < 4; kk++) {
            uint32_t pa[2][4];
#pragma unroll
            for (int mt = 0; mt < 2; mt++) {
                uint32_t roff = (wm * 32 + mt * 16 + (lane & 15)) * 144 +
                                (kk * 16 + ((lane & 16) ? 8 : 0)) * 2;
                ldsm4(pa[mt], bP + roff);
            }
            uint32_t vh[4], vl[4];
            {
                uint32_t roff = (kk * 16 + (lane & 15)) * 144 +
                                (wn * 16 + ((lane & 16) ? 8 : 0)) * 2;
                ldsm4t(vh, bKh + roff);
                ldsm4t(vl, bKl + roff);
            }
#pragma unroll
            for (int mt = 0; mt < 2; mt++) {
                mma16816(acc_o[mt][0], pa[mt], vh[0], vh[1]);
                mma16816(acc_o[mt][1], pa[mt], vh[2], vh[3]);
                mma16816(acc_o[mt][0], pa[mt], vl[0], vl[1]);
                mma16816(acc_o[mt][1], pa[mt], vl[2], vl[3]);
            }
        }
    }

#pragma unroll
    for (int mt = 0; mt < 2; mt++)
#pragma unroll
        for (int nt = 0; nt < 2; nt++) {
            const int row0 = q0 + wm * 32 + mt * 16 + (lane >> 2);
            const int col = hc + wn * 16 + nt * 8 + 2 * (lane & 3);
#pragma unroll
            for (int rh = 0; rh < 2; rh++) {
                const float inv = 1.0f / l_run[mt][rh];
                *reinterpret_cast<float2*>(&O[(long long)(row0 + 8 * rh) * DD_ + col]) =
                    make_float2(acc_o[mt][nt][2 * rh] * inv, acc_o[mt][nt][2 * rh + 1] * inv);
            }
        }
}

// ---------------- LayerNorm over D=512, one block per row ----------------
__global__ void ln_kernel(const float* __restrict__ x, const float* __restrict__ g,
                          const float* __restrict__ b, float* __restrict__ y)
{
    const int row = blockIdx.x;
    const int t = threadIdx.x;
    const float* xr = x + (long long)row * DD_;
    float* yr = y + (long long)row * DD_;

    float4 v = *reinterpret_cast<const float4*>(&xr[t * 4]);
    float s = v.x + v.y + v.z + v.w;
    float ss = v.x * v.x + v.y * v.y + v.z * v.z + v.w * v.w;

    __shared__ float sh[2][4];
#pragma unroll
    for (int o = 16; o > 0; o >>= 1) {
        s += __shfl_xor_sync(0xffffffffu, s, o);
        ss += __shfl_xor_sync(0xffffffffu, ss, o);
    }
    const int w = t >> 5;
    if ((t & 31) == 0) { sh[0][w] = s; sh[1][w] = ss; }
    __syncthreads();
    s = sh[0][0] + sh[0][1] + sh[0][2] + sh[0][3];
    ss = sh[1][0] + sh[1][1] + sh[1][2] + sh[1][3];

    const float mean = s * (1.0f / DD_);
    const float var = ss * (1.0f / DD_) - mean * mean;
    const float rstd = rsqrtf(var + 1e-5f);

    float4 gg = *reinterpret_cast<const float4*>(&g[t * 4]);
    float4 bb = *reinterpret_cast<const float4*>(&b[t * 4]);
    float4 o;
    o.x = (v.x - mean) * rstd * gg.x + bb.x;
    o.y = (v.y - mean) * rstd * gg.y + bb.y;
    o.z = (v.z - mean) * rstd * gg.z + bb.z;
    o.w = (v.w - mean) * rstd * gg.w + bb.w;
    *reinterpret_cast<float4*>(&yr[t * 4]) = o;
}

// ---------------- concat [x0 | h] -> cat ----------------
__global__ void cat_kernel(const float4* __restrict__ x0, const float4* __restrict__ h,
                           float4* __restrict__ cat)
{
    const int i = blockIdx.x * blockDim.x + threadIdx.x;
    const int row = i >> 7, c = i & 127;
    cat[(long long)row * 256 + c] = x0[i];
    cat[(long long)row * 256 + 128 + c] = h[i];
}

// ---------------- per-row reconstruction error (row len 1024) ----------------
__global__ void err_kernel(const float* __restrict__ recon, const float* __restrict__ cat,
                           float* __restrict__ err)
{
    const int row = blockIdx.x;
    const int t = threadIdx.x;
    float4 a = *reinterpret_cast<const float4*>(&recon[(long long)row * 1024 + t * 4]);
    float4 b = *reinterpret_cast<const float4*>(&cat[(long long)row * 1024 + t * 4]);
    float dx = a.x - b.x, dy = a.y - b.y, dz = a.z - b.z, dw = a.w - b.w;
    float s = dx * dx + dy * dy + dz * dz + dw * dw;
    __shared__ float sh[8];
#pragma unroll
    for (int o = 16; o > 0; o >>= 1) s += __shfl_xor_sync(0xffffffffu, s, o);
    if ((t & 31) == 0) sh[t >> 5] = s;
    __syncthreads();
    if (t == 0) {
        float tot = 0.0f;
#pragma unroll
        for (int i = 0; i < 8; i++) tot += sh[i];
        err[row] = tot * (1.0f / 1024.0f);
    }
}

__global__ void minmax_kernel(const float* __restrict__ err, float* __restrict__ mnmx)
{
    const int t = threadIdx.x;
    float mn = 1e30f, mx = -1e30f;
    for (int i = t; i < NN_; i += 1024) {
        float e = err[i];
        mn = fminf(mn, e);
        mx = fmaxf(mx, e);
    }
    __shared__ float smn[32], smx[32];
#pragma unroll
    for (int o = 16; o > 0; o >>= 1) {
        mn = fminf(mn, __shfl_xor_sync(0xffffffffu, mn, o));
        mx = fmaxf(mx, __shfl_xor_sync(0xffffffffu, mx, o));
    }
    if ((t & 31) == 0) { smn[t >> 5] = mn; smx[t >> 5] = mx; }
    __syncthreads();
    if (t == 0) {
#pragma unroll
        for (int i = 1; i < 32; i++) { mn = fminf(mn, smn[i]); mx = fmaxf(mx, smx[i]); }
        mnmx[0] = mn;
        mnmx[1] = mx;
    }
}

__global__ void norm_kernel(const float* __restrict__ err, const float* __restrict__ mnmx,
                            float* __restrict__ out)
{
    const int i = blockIdx.x * blockDim.x + threadIdx.x;
    const float mn = mnmx[0], mx = mnmx[1];
    out[i] = (mx > mn) ? (err[i] - mn) / (mx - mn) : 0.5f;
}

// ---------------- host-side wrappers ----------------
static inline void tf_nt(const float* A, const float* B, const float* bias,
                         const float* extra, float* C, int M, int N, int K,
                         int lda, int ldb, int ldc, int mode)
{
    dim3 grid(N / 64, M / 64);
    gemm_tf<<<grid, 128>>>(A, B, bias, extra, C, M, N, K, lda, ldb, ldc, mode);
}

static inline void ppr_nn(const float* A, const float* B, const float* extra, float* C,
                          int M, int N, int K, float alpha, float beta)
{
    dim3 grid(N / 64, M / 64);
    ppr_gemm<<<grid, 128>>>(A, B, extra, C, M, N, K, K, N, N, alpha, beta);
}

extern "C" void kernel_launch(void* const* d_in, const int* in_sizes, int n_in,
                              void* d_out, int out_size)
{
    const float* x0 = (const float*)d_in[0];
    const float* adj = (const float*)d_in[1];
    const float* Wp = (const float*)d_in[2];
    const float* bp = (const float*)d_in[3];
    const float* ln1g = (const float*)d_in[4];
    const float* ln1b = (const float*)d_in[5];
    const float* Wq = (const float*)d_in[6];
    const float* bq = (const float*)d_in[7];
    const float* Wk = (const float*)d_in[8];
    const float* bk = (const float*)d_in[9];
    const float* Wv = (const float*)d_in[10];
    const float* bv = (const float*)d_in[11];
    const float* Wo = (const float*)d_in[12];
    const float* bo = (const float*)d_in[13];
    const float* ln2g = (const float*)d_in[14];
    const float* ln2b = (const float*)d_in[15];
    const float* W1 = (const float*)d_in[16];
    const float* b1 = (const float*)d_in[17];
    const float* W2 = (const float*)d_in[18];
    const float* b2 = (const float*)d_in[19];
    const float* lnfg = (const float*)d_in[20];
    const float* lnfb = (const float*)d_in[21];
    const float* Wd1 = (const float*)d_in[22];
    const float* bd1 = (const float*)d_in[23];
    const float* Wd2 = (const float*)d_in[24];
    const float* bd2 = (const float*)d_in[25];
    float* out = (float*)d_out;

    float *h1, *h2, *cat, *emb, *y, *q, *k, *v, *o, *ffn, *errp, *mnmxp;
    cudaGetSymbolAddress((void**)&h1, g_h1);
    cudaGetSymbolAddress((void**)&h2, g_h2);
    cudaGetSymbolAddress((void**)&cat, g_cat);
    cudaGetSymbolAddress((void**)&emb, g_emb);
    cudaGetSymbolAddress((void**)&y, g_y);
    cudaGetSymbolAddress((void**)&q, g_q);
    cudaGetSymbolAddress((void**)&k, g_k);
    cudaGetSymbolAddress((void**)&v, g_v);
    cudaGetSymbolAddress((void**)&o, g_o);
    cudaGetSymbolAddress((void**)&ffn, g_ffn);
    cudaGetSymbolAddress((void**)&errp, g_err);
    cudaGetSymbolAddress((void**)&mnmxp, g_mnmx);

    // ---- PPR propagation (exact-ish bf16 3-pass): h <- 0.9*(adj@h) + 0.1*x0 ----
    ppr_nn(adj, x0, x0, h1, NN_, DD_, NN_, 0.9f, 0.1f);
    ppr_nn(adj, h1, x0, h2, NN_, DD_, NN_, 0.9f, 0.1f);
    ppr_nn(adj, h2, x0, h1, NN_, DD_, NN_, 0.9f, 0.1f);

    // ---- cat = [x0 | h], emb = cat @ Wp^T + bp ----
    cat_kernel<<<2048, 256>>>((const float4*)x0, (const float4*)h1, (float4*)cat);
    tf_nt(cat, Wp, bp, nullptr, emb, NN_, DD_, 2 * FF_, 2 * FF_, 2 * FF_, DD_, EP_BIAS);

    // ---- transformer layers ----
    for (int i = 0; i < LL_; i++) {
        ln_kernel<<<NN_, 128>>>(emb, ln1g + i * DD_, ln1b + i * DD_, y);
        tf_nt(y, Wq + (long long)i * DD_ * DD_, bq + i * DD_, nullptr, q,
              NN_, DD_, DD_, DD_, DD_, DD_, EP_BIAS);
        tf_nt(y, Wk + (long long)i * DD_ * DD_, bk + i * DD_, nullptr, k,
              NN_, DD_, DD_, DD_, DD_, DD_, EP_BIAS);
        tf_nt(y, Wv + (long long)i * DD_ * DD_, bv + i * DD_, nullptr, v,
              NN_, DD_, DD_, DD_, DD_, DD_, EP_BIAS);

        // fused attention (scores + softmax + AV), no global scratch
        flash_kernel<<<dim3(NN_ / 64, HH_), 256>>>(q, k, v, o);

        tf_nt(o, Wo + (long long)i * DD_ * DD_, bo + i * DD_, emb, emb,
              NN_, DD_, DD_, DD_, DD_, DD_, EP_BIAS_RES);

        ln_kernel<<<NN_, 128>>>(emb, ln2g + i * DD_, ln2b + i * DD_, y);
        tf_nt(y, W1 + (long long)i * DFF_ * DD_, b1 + i * DFF_, nullptr, ffn,
              NN_, DFF_, DD_, DD_, DD_, DFF_, EP_GELU);
        tf_nt(ffn, W2 + (long long)i * DD_ * DFF_, b2 + i * DD_, emb, emb,
              NN_, DD_, DFF_, DFF_, DFF_, DD_, EP_BIAS_RES);
    }

    // ---- final LN directly into output ----
    ln_kernel<<<NN_, 128>>>(emb, lnfg, lnfb, out);

    // ---- decoder + anomaly scores ----
    tf_nt(out, Wd1, bd1, nullptr, q, NN_, DD_, DD_, DD_, DD_, DD_, EP_RELU);
    tf_nt(q, Wd2, bd2, nullptr, ffn, NN_, 2 * FF_, DD_, DD_, DD_, 2 * FF_, EP_BIAS);
    err_kernel<<<NN_, 256>>>(ffn, cat, errp);
    minmax_kernel<<<1, 1024>>>(errp, mnmxp);
    if (out_size >= NN_ * DD_ + NN_) {
        norm_kernel<<<NN_ / 256, 256>>>(errp, mnmxp, out + (out_size - NN_));
    }
}

// round 15
// speedup vs baseline: 1.4041x; 1.4041x over previous
#include <cuda_runtime.h>
#include <cuda_bf16.h>
#include <math.h>
#include <stdint.h>

// Problem constants
#define NN_ 4096
#define FF_ 512
#define DD_ 512
#define DFF_ 2048
#define LL_ 4
#define HH_ 8

// ---------------- scratch (__device__ globals; no allocation allowed) ----------------
__device__ float g_h1[NN_ * DD_];
__device__ float g_h2[NN_ * DD_];
__device__ float g_cat[NN_ * 2 * FF_];
__device__ float g_emb[NN_ * DD_];
__device__ float g_y[NN_ * DD_];
__device__ float g_qkv[3 * NN_ * DD_];
__device__ float g_o[NN_ * DD_];
__device__ float g_ffn[NN_ * DFF_];
__device__ float g_err[NN_];
__device__ float g_mnmx[2];

enum { EP_NONE = 0, EP_BIAS = 1, EP_BIAS_RES = 2, EP_GELU = 3, EP_RELU = 4, EP_AXPBY = 5 };

// ================= low-level helpers =================
__device__ __forceinline__ uint32_t smem_u32(const void* p) {
    uint32_t a;
    asm("{ .reg .u64 t; cvta.to.shared.u64 t, %1; cvt.u32.u64 %0, t; }" : "=r"(a) : "l"(p));
    return a;
}

__device__ __forceinline__ void ldsm4(uint32_t* r, uint32_t a) {
    asm volatile("ldmatrix.sync.aligned.m8n8.x4.shared.b16 {%0,%1,%2,%3}, [%4];"
                 : "=r"(r[0]), "=r"(r[1]), "=r"(r[2]), "=r"(r[3]) : "r"(a));
}
__device__ __forceinline__ void ldsm4t(uint32_t* r, uint32_t a) {
    asm volatile("ldmatrix.sync.aligned.m8n8.x4.trans.shared.b16 {%0,%1,%2,%3}, [%4];"
                 : "=r"(r[0]), "=r"(r[1]), "=r"(r[2]), "=r"(r[3]) : "r"(a));
}

__device__ __forceinline__ void mma16816(float* d, const uint32_t* a, uint32_t b0, uint32_t b1) {
    asm volatile(
        "mma.sync.aligned.m16n8k16.row.col.f32.bf16.bf16.f32 "
        "{%0,%1,%2,%3}, {%4,%5,%6,%7}, {%8,%9}, {%0,%1,%2,%3};"
        : "+f"(d[0]), "+f"(d[1]), "+f"(d[2]), "+f"(d[3])
        : "r"(a[0]), "r"(a[1]), "r"(a[2]), "r"(a[3]), "r"(b0), "r"(b1));
}

__device__ __forceinline__ void mma_tf32(float* d, const uint32_t* a, uint32_t b0, uint32_t b1) {
    asm volatile(
        "mma.sync.aligned.m16n8k8.row.col.f32.tf32.tf32.f32 "
        "{%0,%1,%2,%3}, {%4,%5,%6,%7}, {%8,%9}, {%0,%1,%2,%3};"
        : "+f"(d[0]), "+f"(d[1]), "+f"(d[2]), "+f"(d[3])
        : "r"(a[0]), "r"(a[1]), "r"(a[2]), "r"(a[3]), "r"(b0), "r"(b1));
}

__device__ __forceinline__ uint32_t f2tf32(float x) {
    uint32_t r;
    asm("cvt.rna.tf32.f32 %0, %1;" : "=r"(r) : "f"(x));
    return r;
}

__device__ __forceinline__ uint32_t cvt_bf16x2(float e0, float e1) {
    uint32_t r;
    asm("cvt.rn.bf16x2.f32 %0, %1, %2;" : "=r"(r) : "f"(e1), "f"(e0));
    return r;
}

// hi/lo split of a pair: hi = top-16-bit truncation (exact), lo = bf16_rn(x - hi)
__device__ __forceinline__ void split_pair(float e0, float e1, uint32_t& hw, uint32_t& lw) {
    uint32_t b0 = __float_as_uint(e0), b1 = __float_as_uint(e1);
    hw = __byte_perm(b0, b1, 0x7632);
    float l0 = e0 - __uint_as_float(b0 & 0xFFFF0000u);
    float l1 = e1 - __uint_as_float(b1 & 0xFFFF0000u);
    lw = cvt_bf16x2(l0, l1);
}

// ================= single-pass TF32 GEMM (R12-proven): 128x128 tile, 256 thr =================
// C[M,N] = A[M,K] B^T + epilogue (NT: B is [N,K] row-major).
__global__ void __launch_bounds__(256)
gemm_tf(const float* __restrict__ A, const float* __restrict__ B,
        const float* __restrict__ bias, const float* __restrict__ extra,
        float* __restrict__ C,
        int M, int N, int K, int lda, int ldb, int ldc, int mode)
{
    __shared__ uint32_t sA[128][36];
    __shared__ uint32_t sB[128][36];

    const int tid = threadIdx.x, lane = tid & 31, wid = tid >> 5;
    const int wm = wid >> 2, wn = wid & 3;
    const int bm0 = blockIdx.y * 128, bn0 = blockIdx.x * 128;

    float acc[4][4][4];
#pragma unroll
    for (int i = 0; i < 4; i++)
#pragma unroll
        for (int j = 0; j < 4; j++)
#pragma unroll
            for (int e = 0; e < 4; e++) acc[i][j][e] = 0.0f;

    const int nc = K / 32;
    const int lrow = tid >> 3, lc4 = (tid & 7) * 4;
    float4 ra[4], rb[4];

#pragma unroll
    for (int i = 0; i < 4; i++) {
        int row = lrow + i * 32;
        ra[i] = *reinterpret_cast<const float4*>(&A[(long long)(bm0 + row) * lda + lc4]);
        rb[i] = *reinterpret_cast<const float4*>(&B[(long long)(bn0 + row) * ldb + lc4]);
    }

    for (int c = 0; c < nc; c++) {
#pragma unroll
        for (int i = 0; i < 4; i++) {
            int row = lrow + i * 32;
            uint4 ua = make_uint4(f2tf32(ra[i].x), f2tf32(ra[i].y), f2tf32(ra[i].z), f2tf32(ra[i].w));
            uint4 ub = make_uint4(f2tf32(rb[i].x), f2tf32(rb[i].y), f2tf32(rb[i].z), f2tf32(rb[i].w));
            *reinterpret_cast<uint4*>(&sA[row][lc4]) = ua;
            *reinterpret_cast<uint4*>(&sB[row][lc4]) = ub;
        }
        __syncthreads();

        if (c + 1 < nc) {
            const int k0 = (c + 1) * 32;
#pragma unroll
            for (int i = 0; i < 4; i++) {
                int row = lrow + i * 32;
                ra[i] = *reinterpret_cast<const float4*>(&A[(long long)(bm0 + row) * lda + k0 + lc4]);
                rb[i] = *reinterpret_cast<const float4*>(&B[(long long)(bn0 + row) * ldb + k0 + lc4]);
            }
        }

        const int g4 = lane >> 2, l4 = lane & 3;
#pragma unroll
        for (int kk = 0; kk < 4; kk++) {
            const int kc = kk * 8 + l4;
            uint32_t af[4][4];
#pragma unroll
            for (int mt = 0; mt < 4; mt++) {
                const int r = wm * 64 + mt * 16 + g4;
                af[mt][0] = sA[r][kc];
                af[mt][1] = sA[r + 8][kc];
                af[mt][2] = sA[r][kc + 4];
                af[mt][3] = sA[r + 8][kc + 4];
            }
            uint32_t bf[4][2];
#pragma unroll
            for (int nt = 0; nt < 4; nt++) {
                const int n = wn * 32 + nt * 8 + g4;
                bf[nt][0] = sB[n][kc];
                bf[nt][1] = sB[n][kc + 4];
            }
#pragma unroll
            for (int mt = 0; mt < 4; mt++)
#pragma unroll
                for (int nt = 0; nt < 4; nt++)
                    mma_tf32(acc[mt][nt], af[mt], bf[nt][0], bf[nt][1]);
        }
        __syncthreads();
    }

#pragma unroll
    for (int mt = 0; mt < 4; mt++)
#pragma unroll
        for (int nt = 0; nt < 4; nt++) {
            const int r0 = bm0 + wm * 64 + mt * 16 + (lane >> 2);
            const int cc = bn0 + wn * 32 + nt * 8 + 2 * (lane & 3);
#pragma unroll
            for (int h = 0; h < 2; h++) {
                const int r = r0 + h * 8;
                float v0 = acc[mt][nt][2 * h], v1 = acc[mt][nt][2 * h + 1];
                const long long off = (long long)r * ldc + cc;
                if (mode == EP_BIAS) {
                    v0 += bias[cc]; v1 += bias[cc + 1];
                } else if (mode == EP_BIAS_RES) {
                    v0 += bias[cc] + extra[off]; v1 += bias[cc + 1] + extra[off + 1];
                } else if (mode == EP_GELU) {
                    v0 += bias[cc]; v1 += bias[cc + 1];
                    v0 = 0.5f * v0 * (1.0f + erff(v0 * 0.7071067811865475f));
                    v1 = 0.5f * v1 * (1.0f + erff(v1 * 0.7071067811865475f));
                } else if (mode == EP_RELU) {
                    v0 = fmaxf(v0 + bias[cc], 0.0f); v1 = fmaxf(v1 + bias[cc + 1], 0.0f);
                }
                *reinterpret_cast<float2*>(&C[off]) = make_float2(v0, v1);
            }
        }
}

// ================= batched QKV TF32 GEMM: z selects (Wq,bq)/(Wk,bk)/(Wv,bv) =================
__global__ void __launch_bounds__(256)
gemm_tf3(const float* __restrict__ A,
         const float* __restrict__ B0, const float* __restrict__ B1, const float* __restrict__ B2,
         const float* __restrict__ bi0, const float* __restrict__ bi1, const float* __restrict__ bi2,
         float* __restrict__ Cb, long long sC)
{
    __shared__ uint32_t sA[128][36];
    __shared__ uint32_t sB[128][36];

    const int tid = threadIdx.x, lane = tid & 31, wid = tid >> 5;
    const int wm = wid >> 2, wn = wid & 3;
    const int bm0 = blockIdx.y * 128, bn0 = blockIdx.x * 128;
    const int z = blockIdx.z;
    const float* B = (z == 0) ? B0 : ((z == 1) ? B1 : B2);
    const float* bias = (z == 0) ? bi0 : ((z == 1) ? bi1 : bi2);
    float* C = Cb + z * sC;

    float acc[4][4][4];
#pragma unroll
    for (int i = 0; i < 4; i++)
#pragma unroll
        for (int j = 0; j < 4; j++)
#pragma unroll
            for (int e = 0; e < 4; e++) acc[i][j][e] = 0.0f;

    const int lrow = tid >> 3, lc4 = (tid & 7) * 4;
    float4 ra[4], rb[4];

#pragma unroll
    for (int i = 0; i < 4; i++) {
        int row = lrow + i * 32;
        ra[i] = *reinterpret_cast<const float4*>(&A[(long long)(bm0 + row) * DD_ + lc4]);
        rb[i] = *reinterpret_cast<const float4*>(&B[(long long)(bn0 + row) * DD_ + lc4]);
    }

    for (int c = 0; c < DD_ / 32; c++) {
#pragma unroll
        for (int i = 0; i < 4; i++) {
            int row = lrow + i * 32;
            uint4 ua = make_uint4(f2tf32(ra[i].x), f2tf32(ra[i].y), f2tf32(ra[i].z), f2tf32(ra[i].w));
            uint4 ub = make_uint4(f2tf32(rb[i].x), f2tf32(rb[i].y), f2tf32(rb[i].z), f2tf32(rb[i].w));
            *reinterpret_cast<uint4*>(&sA[row][lc4]) = ua;
            *reinterpret_cast<uint4*>(&sB[row][lc4]) = ub;
        }
        __syncthreads();

        if (c + 1 < DD_ / 32) {
            const int k0 = (c + 1) * 32;
#pragma unroll
            for (int i = 0; i < 4; i++) {
                int row = lrow + i * 32;
                ra[i] = *reinterpret_cast<const float4*>(&A[(long long)(bm0 + row) * DD_ + k0 + lc4]);
                rb[i] = *reinterpret_cast<const float4*>(&B[(long long)(bn0 + row) * DD_ + k0 + lc4]);
            }
        }

        const int g4 = lane >> 2, l4 = lane & 3;
#pragma unroll
        for (int kk = 0; kk < 4; kk++) {
            const int kc = kk * 8 + l4;
            uint32_t af[4][4];
#pragma unroll
            for (int mt = 0; mt < 4; mt++) {
                const int r = wm * 64 + mt * 16 + g4;
                af[mt][0] = sA[r][kc];
                af[mt][1] = sA[r + 8][kc];
                af[mt][2] = sA[r][kc + 4];
                af[mt][3] = sA[r + 8][kc + 4];
            }
            uint32_t bf[4][2];
#pragma unroll
            for (int nt = 0; nt < 4; nt++) {
                const int n = wn * 32 + nt * 8 + g4;
                bf[nt][0] = sB[n][kc];
                bf[nt][1] = sB[n][kc + 4];
            }
#pragma unroll
            for (int mt = 0; mt < 4; mt++)
#pragma unroll
                for (int nt = 0; nt < 4; nt++)
                    mma_tf32(acc[mt][nt], af[mt], bf[nt][0], bf[nt][1]);
        }
        __syncthreads();
    }

#pragma unroll
    for (int mt = 0; mt < 4; mt++)
#pragma unroll
        for (int nt = 0; nt < 4; nt++) {
            const int r0 = bm0 + wm * 64 + mt * 16 + (lane >> 2);
            const int cc = bn0 + wn * 32 + nt * 8 + 2 * (lane & 3);
#pragma unroll
            for (int h = 0; h < 2; h++) {
                const int r = r0 + h * 8;
                const long long off = (long long)r * DD_ + cc;
                *reinterpret_cast<float2*>(&C[off]) = make_float2(
                    acc[mt][nt][2 * h] + bias[cc], acc[mt][nt][2 * h + 1] + bias[cc + 1]);
            }
        }
}

// ================= PPR split-bf16 GEMM (R12-proven): 128x128, NN, 3-pass =================
__global__ void __launch_bounds__(256)
ppr_gemm(const float* __restrict__ A, const float* __restrict__ B,
         const float* __restrict__ extra, float* __restrict__ C,
         int K, float alpha, float beta)
{
    constexpr int AST = 40;
    constexpr int APL = 128 * AST * 2;
    constexpr int BST = 136;               // 128 + 8 pad (bf16 elems)
    constexpr int BPL = 32 * BST * 2;

    __shared__ __align__(16) char smbuf[2 * APL + 2 * BPL];

    const uint32_t sbase = smem_u32(smbuf);
    const int tid = threadIdx.x, lane = tid & 31, wid = tid >> 5;
    const int wm = wid >> 2, wn = wid & 3;
    const int bm0 = blockIdx.y * 128, bn0 = blockIdx.x * 128;

    float acc[4][4][4];
#pragma unroll
    for (int i = 0; i < 4; i++)
#pragma unroll
        for (int j = 0; j < 4; j++)
#pragma unroll
            for (int e = 0; e < 4; e++) acc[i][j][e] = 0.0f;

    const int nc = K / 32;
    float4 ra[4], rb[4];

    {
#pragma unroll
        for (int i = 0; i < 4; i++) {
            int row = (tid >> 3) + i * 32, c4 = (tid & 7) * 4;
            ra[i] = *reinterpret_cast<const float4*>(&A[(long long)(bm0 + row) * K + c4]);
        }
#pragma unroll
        for (int i = 0; i < 4; i++) {
            int k = tid >> 5, n4 = (tid & 31) * 4;
            rb[i] = *reinterpret_cast<const float4*>(&B[(long long)(k + i * 8) * DD_ + bn0 + n4]);
        }
    }

    for (int c = 0; c < nc; c++) {
#pragma unroll
        for (int i = 0; i < 4; i++) {
            int row = (tid >> 3) + i * 32, c4 = (tid & 7) * 4;
            uint32_t h0, l0, h1, l1;
            split_pair(ra[i].x, ra[i].y, h0, l0);
            split_pair(ra[i].z, ra[i].w, h1, l1);
            uint32_t off = row * (AST * 2) + c4 * 2;
            *reinterpret_cast<uint2*>(smbuf + off) = make_uint2(h0, h1);
            *reinterpret_cast<uint2*>(smbuf + APL + off) = make_uint2(l0, l1);
        }
#pragma unroll
        for (int i = 0; i < 4; i++) {
            int k = (tid >> 5) + i * 8, n4 = (tid & 31) * 4;
            float e[4] = {rb[i].x, rb[i].y, rb[i].z, rb[i].w};
#pragma unroll
            for (int j = 0; j < 4; j++) {
                uint32_t xb = __float_as_uint(e[j]);
                float lo = e[j] - __uint_as_float(xb & 0xFFFF0000u);
                uint32_t off = 2 * APL + k * (BST * 2) + (n4 + j) * 2;
                *reinterpret_cast<uint16_t*>(smbuf + off) = (uint16_t)(xb >> 16);
                __nv_bfloat16 bl = __float2bfloat16(lo);
                *reinterpret_cast<uint16_t*>(smbuf + BPL + off) =
                    *reinterpret_cast<uint16_t*>(&bl);
            }
        }
        __syncthreads();

        if (c + 1 < nc) {
            const int k0 = (c + 1) * 32;
#pragma unroll
            for (int i = 0; i < 4; i++) {
                int row = (tid >> 3) + i * 32, c4 = (tid & 7) * 4;
                ra[i] = *reinterpret_cast<const float4*>(
                    &A[(long long)(bm0 + row) * K + k0 + c4]);
            }
#pragma unroll
            for (int i = 0; i < 4; i++) {
                int k = tid >> 5, n4 = (tid & 31) * 4;
                rb[i] = *reinterpret_cast<const float4*>(
                    &B[(long long)(k0 + k + i * 8) * DD_ + bn0 + n4]);
            }
        }

        const uint32_t aAddr = sbase + (wm * 64 + (lane & 15)) * (AST * 2) +
                               (((lane & 16) ? 8 : 0)) * 2;
        const uint32_t bAddr = sbase + 2 * APL + (lane & 15) * (BST * 2) +
                               (wn * 32 + ((lane & 16) ? 8 : 0)) * 2;

#pragma unroll
        for (int kk = 0; kk < 2; kk++) {
            uint32_t ah[4][4], al[4][4];
#pragma unroll
            for (int mt = 0; mt < 4; mt++) {
                uint32_t adr = aAddr + mt * 16 * (AST * 2) + kk * 32;
                ldsm4(ah[mt], adr);
                ldsm4(al[mt], adr + APL);
            }
            uint32_t bh[4][2], bl[4][2];
#pragma unroll
            for (int p = 0; p < 2; p++) {
                uint32_t r[4];
                uint32_t adr = bAddr + kk * 16 * (BST * 2) + p * 32;
                ldsm4t(r, adr);
                bh[2 * p][0] = r[0]; bh[2 * p][1] = r[1];
                bh[2 * p + 1][0] = r[2]; bh[2 * p + 1][1] = r[3];
                ldsm4t(r, adr + BPL);
                bl[2 * p][0] = r[0]; bl[2 * p][1] = r[1];
                bl[2 * p + 1][0] = r[2]; bl[2 * p + 1][1] = r[3];
            }
#pragma unroll
            for (int mt = 0; mt < 4; mt++)
#pragma unroll
                for (int nt = 0; nt < 4; nt++) {
                    mma16816(acc[mt][nt], ah[mt], bh[nt][0], bh[nt][1]);
                    mma16816(acc[mt][nt], ah[mt], bl[nt][0], bl[nt][1]);
                    mma16816(acc[mt][nt], al[mt], bh[nt][0], bh[nt][1]);
                }
        }
        __syncthreads();
    }

#pragma unroll
    for (int mt = 0; mt < 4; mt++)
#pragma unroll
        for (int nt = 0; nt < 4; nt++) {
            const int r0 = bm0 + wm * 64 + mt * 16 + (lane >> 2);
            const int cc = bn0 + wn * 32 + nt * 8 + 2 * (lane & 3);
#pragma unroll
            for (int h = 0; h < 2; h++) {
                const int r = r0 + h * 8;
                const long long off = (long long)r * DD_ + cc;
                float v0 = alpha * acc[mt][nt][2 * h] + beta * extra[off];
                float v1 = alpha * acc[mt][nt][2 * h + 1] + beta * extra[off + 1];
                *reinterpret_cast<float2*>(&C[off]) = make_float2(v0, v1);
            }
        }
}

// ================= fused flash attention: Q hi/lo, K/V single rn-bf16 planes =================
// QK = 2-pass (qh*k + ql*k), PV = 1-pass. Structure otherwise identical to validated R11.
__global__ void __launch_bounds__(256)
flash_kernel(const float* __restrict__ Q, const float* __restrict__ K,
             const float* __restrict__ V, float* __restrict__ O)
{
    __shared__ __align__(16) char sQh[64 * 144], sQl[64 * 144];
    __shared__ __align__(16) char sKV[64 * 144];
    __shared__ __align__(16) char sP[64 * 144];
    __shared__ float redM[64][4];
    __shared__ float redS[64][4];

    const int tid = threadIdx.x, lane = tid & 31, wid = tid >> 5;
    const int wm = wid >> 2, wn = wid & 3;
    const int q0 = blockIdx.x * 64;
    const int hc = blockIdx.y * 64;

    const uint32_t bQh = smem_u32(sQh), bQl = smem_u32(sQl);
    const uint32_t bKV = smem_u32(sKV);
    const uint32_t bP = smem_u32(sP);

    // ---- load Q block (64 x 64), split hi/lo ----
#pragma unroll
    for (int i = 0; i < 4; i++) {
        int idx = tid + i * 256;
        int row = idx >> 4, c4 = (idx & 15) * 4;
        float4 u = *reinterpret_cast<const float4*>(&Q[(long long)(q0 + row) * DD_ + hc + c4]);
        uint32_t h0, l0, h1, l1;
        split_pair(u.x, u.y, h0, l0);
        split_pair(u.z, u.w, h1, l1);
        uint32_t off = row * 144 + c4 * 2;
        *reinterpret_cast<uint2*>(sQh + off) = make_uint2(h0, h1);
        *reinterpret_cast<uint2*>(sQl + off) = make_uint2(l0, l1);
    }

    float acc_o[2][2][4];
    float m_run[2][2], l_run[2][2];
#pragma unroll
    for (int mt = 0; mt < 2; mt++) {
#pragma unroll
        for (int nt = 0; nt < 2; nt++)
#pragma unroll
            for (int e = 0; e < 4; e++) acc_o[mt][nt][e] = 0.0f;
        m_run[mt][0] = m_run[mt][1] = -1e30f;
        l_run[mt][0] = l_run[mt][1] = 0.0f;
    }

    const int rbase = wm * 32 + (lane >> 2);

    for (int c = 0; c < NN_ / 64; c++) {
        __syncthreads();  // prev PV reads of KV/P done

        // ---- K chunk (single rn-bf16 plane) ----
#pragma unroll
        for (int i = 0; i < 4; i++) {
            int idx = tid + i * 256;
            int row = idx >> 4, c4 = (idx & 15) * 4;
            float4 u = *reinterpret_cast<const float4*>(
                &K[(long long)(c * 64 + row) * DD_ + hc + c4]);
            uint32_t w0 = cvt_bf16x2(u.x, u.y), w1 = cvt_bf16x2(u.z, u.w);
            *reinterpret_cast<uint2*>(sKV + row * 144 + c4 * 2) = make_uint2(w0, w1);
        }
        __syncthreads();

        // ---- S = Q K^T (2-pass: qh*k + ql*k) ----
        float s[2][2][4];
#pragma unroll
        for (int mt = 0; mt < 2; mt++)
#pragma unroll
            for (int nt = 0; nt < 2; nt++)
#pragma unroll
                for (int e = 0; e < 4; e++) s[mt][nt][e] = 0.0f;

#pragma unroll
        for (int kk = 0; kk < 4; kk++) {
            const uint32_t colA = (kk * 16 + ((lane & 16) ? 8 : 0)) * 2;
            uint32_t qh[2][4], ql[2][4];
#pragma unroll
            for (int mt = 0; mt < 2; mt++) {
                uint32_t roff = (wm * 32 + mt * 16 + (lane & 15)) * 144 + colA;
                ldsm4(qh[mt], bQh + roff);
                ldsm4(ql[mt], bQl + roff);
            }
            uint32_t kf[4];
            {
                uint32_t roff = (wn * 16 + (lane & 7) + ((lane & 16) ? 8 : 0)) * 144 +
                                (kk * 16 + ((lane & 8) ? 8 : 0)) * 2;
                ldsm4(kf, bKV + roff);
            }
#pragma unroll
            for (int mt = 0; mt < 2; mt++) {
                mma16816(s[mt][0], qh[mt], kf[0], kf[1]);
                mma16816(s[mt][1], qh[mt], kf[2], kf[3]);
                mma16816(s[mt][0], ql[mt], kf[0], kf[1]);
                mma16816(s[mt][1], ql[mt], kf[2], kf[3]);
            }
        }

        // ---- row max (warp-local then CTA) ----
#pragma unroll
        for (int mt = 0; mt < 2; mt++)
#pragma unroll
            for (int rh = 0; rh < 2; rh++) {
                float mp = fmaxf(fmaxf(s[mt][0][2 * rh], s[mt][0][2 * rh + 1]),
                                 fmaxf(s[mt][1][2 * rh], s[mt][1][2 * rh + 1]));
                mp = fmaxf(mp, __shfl_xor_sync(0xffffffffu, mp, 1));
                mp = fmaxf(mp, __shfl_xor_sync(0xffffffffu, mp, 2));
                if ((lane & 3) == 0) redM[rbase + mt * 16 + 8 * rh][wn] = mp;
            }
        __syncthreads();

        float f[2][2], sum_p[2][2];
#pragma unroll
        for (int mt = 0; mt < 2; mt++)
#pragma unroll
            for (int rh = 0; rh < 2; rh++) {
                const int row = rbase + mt * 16 + 8 * rh;
                float mc = fmaxf(fmaxf(redM[row][0], redM[row][1]),
                                 fmaxf(redM[row][2], redM[row][3]));
                float mn = fmaxf(m_run[mt][rh], mc);
                f[mt][rh] = __expf(m_run[mt][rh] - mn);
                m_run[mt][rh] = mn;
                sum_p[mt][rh] = 0.0f;
            }

        // ---- p = exp(s - m), store P (bf16), partial sums; scale O ----
#pragma unroll
        for (int mt = 0; mt < 2; mt++)
#pragma unroll
            for (int nt = 0; nt < 2; nt++)
#pragma unroll
                for (int rh = 0; rh < 2; rh++) {
                    float p0 = __expf(s[mt][nt][2 * rh] - m_run[mt][rh]);
                    float p1 = __expf(s[mt][nt][2 * rh + 1] - m_run[mt][rh]);
                    sum_p[mt][rh] += p0 + p1;
                    const int row = rbase + mt * 16 + 8 * rh;
                    const int col = wn * 16 + nt * 8 + 2 * (lane & 3);
                    *reinterpret_cast<uint32_t*>(sP + row * 144 + col * 2) = cvt_bf16x2(p0, p1);
                }
#pragma unroll
        for (int mt = 0; mt < 2; mt++)
#pragma unroll
            for (int nt = 0; nt < 2; nt++)
#pragma unroll
                for (int e = 0; e < 4; e++) acc_o[mt][nt][e] *= f[mt][e >> 1];

#pragma unroll
        for (int mt = 0; mt < 2; mt++)
#pragma unroll
            for (int rh = 0; rh < 2; rh++) {
                float sp = sum_p[mt][rh];
                sp += __shfl_xor_sync(0xffffffffu, sp, 1);
                sp += __shfl_xor_sync(0xffffffffu, sp, 2);
                if ((lane & 3) == 0) redS[rbase + mt * 16 + 8 * rh][wn] = sp;
            }
        __syncthreads();
#pragma unroll
        for (int mt = 0; mt < 2; mt++)
#pragma unroll
            for (int rh = 0; rh < 2; rh++) {
                const int row = rbase + mt * 16 + 8 * rh;
                float sc = redS[row][0] + redS[row][1] + redS[row][2] + redS[row][3];
                l_run[mt][rh] = l_run[mt][rh] * f[mt][rh] + sc;
            }

        // ---- V chunk overwrites KV buffer (single rn-bf16 plane) ----
#pragma unroll
        for (int i = 0; i < 4; i++) {
            int idx = tid + i * 256;
            int row = idx >> 4, c4 = (idx & 15) * 4;
            float4 u = *reinterpret_cast<const float4*>(
                &V[(long long)(c * 64 + row) * DD_ + hc + c4]);
            uint32_t w0 = cvt_bf16x2(u.x, u.y), w1 = cvt_bf16x2(u.z, u.w);
            *reinterpret_cast<uint2*>(sKV + row * 144 + c4 * 2) = make_uint2(w0, w1);
        }
        __syncthreads();

        // ---- O += P V (both bf16, 1 pass) ----
#pragma unroll
        for (int kk = 0; kk < 4; kk++) {
            uint32_t pa[2][4];
#pragma unroll
            for (int mt = 0; mt < 2; mt++) {
                uint32_t roff = (wm * 32 + mt * 16 + (lane & 15)) * 144 +
                                (kk * 16 + ((lane & 16) ? 8 : 0)) * 2;
                ldsm4(pa[mt], bP + roff);
            }
            uint32_t vf[4];
            {
                uint32_t roff = (kk * 16 + (lane & 15)) * 144 +
                                (wn * 16 + ((lane & 16) ? 8 : 0)) * 2;
                ldsm4t(vf, bKV + roff);
            }
#pragma unroll
            for (int mt = 0; mt < 2; mt++) {
                mma16816(acc_o[mt][0], pa[mt], vf[0], vf[1]);
                mma16816(acc_o[mt][1], pa[mt], vf[2], vf[3]);
            }
        }
    }

    // ---- normalize and store O ----
#pragma unroll
    for (int mt = 0; mt < 2; mt++)
#pragma unroll
        for (int nt = 0; nt < 2; nt++) {
            const int row0 = q0 + wm * 32 + mt * 16 + (lane >> 2);
            const int col = hc + wn * 16 + nt * 8 + 2 * (lane & 3);
#pragma unroll
            for (int rh = 0; rh < 2; rh++) {
                const float inv = 1.0f / l_run[mt][rh];
                *reinterpret_cast<float2*>(&O[(long long)(row0 + 8 * rh) * DD_ + col]) =
                    make_float2(acc_o[mt][nt][2 * rh] * inv, acc_o[mt][nt][2 * rh + 1] * inv);
            }
        }
}

// ---------------- LayerNorm over D=512, one block per row ----------------
__global__ void ln_kernel(const float* __restrict__ x, const float* __restrict__ g,
                          const float* __restrict__ b, float* __restrict__ y)
{
    const int row = blockIdx.x;
    const int t = threadIdx.x;
    const float* xr = x + (long long)row * DD_;
    float* yr = y + (long long)row * DD_;

    float4 v = *reinterpret_cast<const float4*>(&xr[t * 4]);
    float s = v.x + v.y + v.z + v.w;
    float ss = v.x * v.x + v.y * v.y + v.z * v.z + v.w * v.w;

    __shared__ float sh[2][4];
#pragma unroll
    for (int o = 16; o > 0; o >>= 1) {
        s += __shfl_xor_sync(0xffffffffu, s, o);
        ss += __shfl_xor_sync(0xffffffffu, ss, o);
    }
    const int w = t >> 5;
    if ((t & 31) == 0) { sh[0][w] = s; sh[1][w] = ss; }
    __syncthreads();
    s = sh[0][0] + sh[0][1] + sh[0][2] + sh[0][3];
    ss = sh[1][0] + sh[1][1] + sh[1][2] + sh[1][3];

    const float mean = s * (1.0f / DD_);
    const float var = ss * (1.0f / DD_) - mean * mean;
    const float rstd = rsqrtf(var + 1e-5f);

    float4 gg = *reinterpret_cast<const float4*>(&g[t * 4]);
    float4 bb = *reinterpret_cast<const float4*>(&b[t * 4]);
    float4 o;
    o.x = (v.x - mean) * rstd * gg.x + bb.x;
    o.y = (v.y - mean) * rstd * gg.y + bb.y;
    o.z = (v.z - mean) * rstd * gg.z + bb.z;
    o.w = (v.w - mean) * rstd * gg.w + bb.w;
    *reinterpret_cast<float4*>(&yr[t * 4]) = o;
}

// ---------------- concat [x0 | h] -> cat ----------------
__global__ void cat_kernel(const float4* __restrict__ x0, const float4* __restrict__ h,
                           float4* __restrict__ cat)
{
    const int i = blockIdx.x * blockDim.x + threadIdx.x;
    const int row = i >> 7, c = i & 127;
    cat[(long long)row * 256 + c] = x0[i];
    cat[(long long)row * 256 + 128 + c] = h[i];
}

// ---------------- per-row reconstruction error (row len 1024) ----------------
__global__ void err_kernel(const float* __restrict__ recon, const float* __restrict__ cat,
                           float* __restrict__ err)
{
    const int row = blockIdx.x;
    const int t = threadIdx.x;
    float4 a = *reinterpret_cast<const float4*>(&recon[(long long)row * 1024 + t * 4]);
    float4 b = *reinterpret_cast<const float4*>(&cat[(long long)row * 1024 + t * 4]);
    float dx = a.x - b.x, dy = a.y - b.y, dz = a.z - b.z, dw = a.w - b.w;
    float s = dx * dx + dy * dy + dz * dz + dw * dw;
    __shared__ float sh[8];
#pragma unroll
    for (int o = 16; o > 0; o >>= 1) s += __shfl_xor_sync(0xffffffffu, s, o);
    if ((t & 31) == 0) sh[t >> 5] = s;
    __syncthreads();
    if (t == 0) {
        float tot = 0.0f;
#pragma unroll
        for (int i = 0; i < 8; i++) tot += sh[i];
        err[row] = tot * (1.0f / 1024.0f);
    }
}

__global__ void minmax_kernel(const float* __restrict__ err, float* __restrict__ mnmx)
{
    const int t = threadIdx.x;
    float mn = 1e30f, mx = -1e30f;
    for (int i = t; i < NN_; i += 1024) {
        float e = err[i];
        mn = fminf(mn, e);
        mx = fmaxf(mx, e);
    }
    __shared__ float smn[32], smx[32];
#pragma unroll
    for (int o = 16; o > 0; o >>= 1) {
        mn = fminf(mn, __shfl_xor_sync(0xffffffffu, mn, o));
        mx = fmaxf(mx, __shfl_xor_sync(0xffffffffu, mx, o));
    }
    if ((t & 31) == 0) { smn[t >> 5] = mn; smx[t >> 5] = mx; }
    __syncthreads();
    if (t == 0) {
#pragma unroll
        for (int i = 1; i < 32; i++) { mn = fminf(mn, smn[i]); mx = fmaxf(mx, smx[i]); }
        mnmx[0] = mn;
        mnmx[1] = mx;
    }
}

__global__ void norm_kernel(const float* __restrict__ err, const float* __restrict__ mnmx,
                            float* __restrict__ out)
{
    const int i = blockIdx.x * blockDim.x + threadIdx.x;
    const float mn = mnmx[0], mx = mnmx[1];
    out[i] = (mx > mn) ? (err[i] - mn) / (mx - mn) : 0.5f;
}

// ---------------- host-side wrappers ----------------
static inline void tf_nt(const float* A, const float* B, const float* bias,
                         const float* extra, float* C, int M, int N, int K,
                         int lda, int ldb, int ldc, int mode)
{
    dim3 grid(N / 128, M / 128);
    gemm_tf<<<grid, 256>>>(A, B, bias, extra, C, M, N, K, lda, ldb, ldc, mode);
}

extern "C" void kernel_launch(void* const* d_in, const int* in_sizes, int n_in,
                              void* d_out, int out_size)
{
    const float* x0 = (const float*)d_in[0];
    const float* adj = (const float*)d_in[1];
    const float* Wp = (const float*)d_in[2];
    const float* bp = (const float*)d_in[3];
    const float* ln1g = (const float*)d_in[4];
    const float* ln1b = (const float*)d_in[5];
    const float* Wq = (const float*)d_in[6];
    const float* bq = (const float*)d_in[7];
    const float* Wk = (const float*)d_in[8];
    const float* bk = (const float*)d_in[9];
    const float* Wv = (const float*)d_in[10];
    const float* bv = (const float*)d_in[11];
    const float* Wo = (const float*)d_in[12];
    const float* bo = (const float*)d_in[13];
    const float* ln2g = (const float*)d_in[14];
    const float* ln2b = (const float*)d_in[15];
    const float* W1 = (const float*)d_in[16];
    const float* b1 = (const float*)d_in[17];
    const float* W2 = (const float*)d_in[18];
    const float* b2 = (const float*)d_in[19];
    const float* lnfg = (const float*)d_in[20];
    const float* lnfb = (const float*)d_in[21];
    const float* Wd1 = (const float*)d_in[22];
    const float* bd1 = (const float*)d_in[23];
    const float* Wd2 = (const float*)d_in[24];
    const float* bd2 = (const float*)d_in[25];
    float* out = (float*)d_out;

    float *h1, *h2, *cat, *emb, *y, *qkv, *o, *ffn, *errp, *mnmxp;
    cudaGetSymbolAddress((void**)&h1, g_h1);
    cudaGetSymbolAddress((void**)&h2, g_h2);
    cudaGetSymbolAddress((void**)&cat, g_cat);
    cudaGetSymbolAddress((void**)&emb, g_emb);
    cudaGetSymbolAddress((void**)&y, g_y);
    cudaGetSymbolAddress((void**)&qkv, g_qkv);
    cudaGetSymbolAddress((void**)&o, g_o);
    cudaGetSymbolAddress((void**)&ffn, g_ffn);
    cudaGetSymbolAddress((void**)&errp, g_err);
    cudaGetSymbolAddress((void**)&mnmxp, g_mnmx);

    const long long ND = (long long)NN_ * DD_;

    // ---- PPR propagation (exact-ish bf16 3-pass): h <- 0.9*(adj@h) + 0.1*x0 ----
    {
        dim3 grid(DD_ / 128, NN_ / 128);
        ppr_gemm<<<grid, 256>>>(adj, x0, x0, h1, NN_, 0.9f, 0.1f);
        ppr_gemm<<<grid, 256>>>(adj, h1, x0, h2, NN_, 0.9f, 0.1f);
        ppr_gemm<<<grid, 256>>>(adj, h2, x0, h1, NN_, 0.9f, 0.1f);
    }

    // ---- cat = [x0 | h], emb = cat @ Wp^T + bp ----
    cat_kernel<<<2048, 256>>>((const float4*)x0, (const float4*)h1, (float4*)cat);
    tf_nt(cat, Wp, bp, nullptr, emb, NN_, DD_, 2 * FF_, 2 * FF_, 2 * FF_, DD_, EP_BIAS);

    // ---- transformer layers ----
    for (int i = 0; i < LL_; i++) {
        ln_kernel<<<NN_, 128>>>(emb, ln1g + i * DD_, ln1b + i * DD_, y);
        // batched QKV (z selects weight/bias), writes qkv[z]
        {
            dim3 grid(DD_ / 128, NN_ / 128, 3);
            gemm_tf3<<<grid, 256>>>(y,
                                    Wq + (long long)i * DD_ * DD_,
                                    Wk + (long long)i * DD_ * DD_,
                                    Wv + (long long)i * DD_ * DD_,
                                    bq + i * DD_, bk + i * DD_, bv + i * DD_,
                                    qkv, ND);
        }

        // fused attention (scores + softmax + AV), no global scratch
        flash_kernel<<<dim3(NN_ / 64, HH_), 256>>>(qkv, qkv + ND, qkv + 2 * ND, o);

        tf_nt(o, Wo + (long long)i * DD_ * DD_, bo + i * DD_, emb, emb,
              NN_, DD_, DD_, DD_, DD_, DD_, EP_BIAS_RES);

        ln_kernel<<<NN_, 128>>>(emb, ln2g + i * DD_, ln2b + i * DD_, y);
        tf_nt(y, W1 + (long long)i * DFF_ * DD_, b1 + i * DFF_, nullptr, ffn,
              NN_, DFF_, DD_, DD_, DD_, DFF_, EP_GELU);
        tf_nt(ffn, W2 + (long long)i * DD_ * DFF_, b2 + i * DD_, emb, emb,
              NN_, DD_, DFF_, DFF_, DFF_, DD_, EP_BIAS_RES);
    }

    // ---- final LN directly into output ----
    ln_kernel<<<NN_, 128>>>(emb, lnfg, lnfb, out);

    // ---- decoder + anomaly scores ----
    tf_nt(out, Wd1, bd1, nullptr, qkv, NN_, DD_, DD_, DD_, DD_, DD_, EP_RELU);
    tf_nt(qkv, Wd2, bd2, nullptr, ffn, NN_, 2 * FF_, DD_, DD_, DD_, 2 * FF_, EP_BIAS);
    err_kernel<<<NN_, 256>>>(ffn, cat, errp);
    minmax_kernel<<<1, 1024>>>(errp, mnmxp);
    if (out_size >= NN_ * DD_ + NN_) {
        norm_kernel<<<NN_ / 256, 256>>>(errp, mnmxp, out + (out_size - NN_));
    }
}